// round 1
// baseline (speedup 1.0000x reference)
#include <cuda_runtime.h>
#include <cstdint>

// Problem constants (shapes are fixed for this dataset entry).
#define R_DIM 64
#define I_DIM 256
#define O_DIM 256
#define T_E   8     // entity rows per block in the main kernel
#define MAIN_THREADS 128   // each thread owns 2 adjacent output columns (f32x2)

// Scratch: W_sum[r][o] (deterministic two-phase would need partials; single
// 64-block kernel is deterministic and fast enough).
__device__ float g_wsum[R_DIM * O_DIM];

// ---------------------------------------------------------------------------
// Kernel 1: W_sum[r][o] = sum_i W[r][i][o].  grid(64), block(256).
// Per iteration i the block reads W[r, i, 0:256] = 1KB contiguous (coalesced).
// ---------------------------------------------------------------------------
__global__ void wsum_kernel(const float* __restrict__ W) {
    const int r = blockIdx.x;
    const int o = threadIdx.x;
    const float* base = W + (size_t)r * I_DIM * O_DIM + o;
    float s = 0.f;
#pragma unroll 8
    for (int i = 0; i < I_DIM; i++) {
        s += base[(size_t)i * O_DIM];
    }
    g_wsum[r * O_DIM + o] = s;
}

// Packed fp32x2 FMA (Blackwell): d = a*b + c elementwise on two packed f32.
__device__ __forceinline__ unsigned long long ffma2(unsigned long long a,
                                                    unsigned long long b,
                                                    unsigned long long c) {
    unsigned long long d;
    asm("fma.rn.f32x2 %0, %1, %2, %3;" : "=l"(d) : "l"(a), "l"(b), "l"(c));
    return d;
}

__device__ __forceinline__ unsigned long long pack2(float lo, float hi) {
    unsigned long long v;
    asm("mov.b64 %0, {%1, %2};" : "=l"(v) : "f"(lo), "f"(hi));
    return v;
}

// ---------------------------------------------------------------------------
// Kernel 2 (fused main): for a tile of T_E entity rows
//   xs[t]      = sum_j x[e,j]                       (warp-per-row reduction)
//   csr2[t][r] = {xs[t]/cs[e,r], xs[t]/cs[e,r]}     (scale folded into csr)
//   out[e, 2t:2t+2] = sum_r W_sum[r, 2t:2t+2] (*) csr2[t][r]   via FFMA2
// W_sum column pair lives in 64 packed registers per thread, loaded once per
// block (L1-resident after the first block on each SM).
// ---------------------------------------------------------------------------
__global__ __launch_bounds__(MAIN_THREADS)
void rgcn_main_kernel(const float* __restrict__ x,
                      const float* __restrict__ cs,
                      float* __restrict__ out,
                      int E) {
    __shared__ float xs[T_E];
    __shared__ __align__(16) unsigned long long csr2[T_E * R_DIM];

    const int tid  = threadIdx.x;
    const int e0   = blockIdx.x * T_E;
    const int warp = tid >> 5;
    const int lane = tid & 31;

    // --- Phase A: W_sum column pair -> registers (64 x LDG.64, coalesced) ---
    unsigned long long w2[R_DIM];
    const float2* wsum2 = reinterpret_cast<const float2*>(g_wsum);
#pragma unroll
    for (int r = 0; r < R_DIM; r++) {
        float2 v = wsum2[r * (O_DIM / 2) + tid];
        w2[r] = pack2(v.x, v.y);
    }

    // --- Phase B: x row sums, one warp per row (2 rows per warp) ---
    for (int t = warp; t < T_E; t += MAIN_THREADS / 32) {
        const int e = e0 + t;
        float s = 0.f;
        if (e < E) {
            const float4* row = reinterpret_cast<const float4*>(x + (size_t)e * I_DIM);
            float4 a = row[lane];
            float4 b = row[lane + 32];
            s = (a.x + a.y) + (a.z + a.w) + (b.x + b.y) + (b.z + b.w);
        }
#pragma unroll
        for (int off = 16; off > 0; off >>= 1)
            s += __shfl_xor_sync(0xffffffffu, s, off);
        if (lane == 0) xs[t] = s;
    }
    __syncthreads();

    // --- Phase C: csr2[t][r] = dup(xs[t] / cs[e,r]) (reciprocal+scale in one div)
#pragma unroll
    for (int k = 0; k < (T_E * R_DIM) / MAIN_THREADS; k++) {
        const int idx = k * MAIN_THREADS + tid;
        const int t = idx >> 6;          // /R_DIM
        const int r = idx & (R_DIM - 1);
        const int e = e0 + t;
        float v = 0.f;
        if (e < E) v = xs[t] / cs[(size_t)e * R_DIM + r];
        csr2[idx] = pack2(v, v);
    }
    __syncthreads();

    // --- Phase D: 8 independent FFMA2 chains; LDS.128 feeds 2 r-steps ---
    unsigned long long acc[T_E];
#pragma unroll
    for (int t = 0; t < T_E; t++) acc[t] = 0ull;

#pragma unroll
    for (int r = 0; r < R_DIM; r += 2) {
#pragma unroll
        for (int t = 0; t < T_E; t++) {
            ulonglong2 c = *reinterpret_cast<const ulonglong2*>(&csr2[t * R_DIM + r]);
            acc[t] = ffma2(w2[r],     c.x, acc[t]);
            acc[t] = ffma2(w2[r + 1], c.y, acc[t]);
        }
    }

    // --- Epilogue: packed 8B stores, coalesced per row ---
#pragma unroll
    for (int t = 0; t < T_E; t++) {
        const int e = e0 + t;
        if (e < E) {
            float2 v;
            asm("mov.b64 {%0, %1}, %2;" : "=f"(v.x), "=f"(v.y) : "l"(acc[t]));
            reinterpret_cast<float2*>(out)[(size_t)e * (O_DIM / 2) + tid] = v;
        }
    }
}

// ---------------------------------------------------------------------------
// Launch. Inputs (metadata order): x (E*256 f32), cs (E*64 f32),
// W (64*256*256 f32), edge_index (2*N int64, UNUSED by the reference math).
// Output: E*256 f32.
// ---------------------------------------------------------------------------
extern "C" void kernel_launch(void* const* d_in, const int* in_sizes, int n_in,
                              void* d_out, int out_size) {
    const float* x  = (const float*)d_in[0];
    const float* cs = (const float*)d_in[1];
    const float* W  = (const float*)d_in[2];
    float* out = (float*)d_out;

    const int E = in_sizes[0] / I_DIM;

    wsum_kernel<<<R_DIM, O_DIM>>>(W);
    const int grid = (E + T_E - 1) / T_E;
    rgcn_main_kernel<<<grid, MAIN_THREADS>>>(x, cs, out, E);
}

// round 2
// speedup vs baseline: 1.7540x; 1.7540x over previous
#include <cuda_runtime.h>
#include <cstdint>

// Problem constants (shapes fixed for this dataset entry).
#define R_DIM 64
#define I_DIM 256
#define O_DIM 256
#define T_E   8            // entity rows per block
#define MAIN_THREADS 128   // each thread owns 2 adjacent output columns (f32x2)
#define R_CHUNK 16         // r-chunking: w2 register footprint = 2*R_CHUNK regs

// Scratch: W_sum[r][o].
__device__ float g_wsum[R_DIM * O_DIM];

// ---------------------------------------------------------------------------
// Kernel 1: W_sum[r][o] = sum_i W[r][i][o].  grid(64), block(256).
// ---------------------------------------------------------------------------
__global__ void wsum_kernel(const float* __restrict__ W) {
    const int r = blockIdx.x;
    const int o = threadIdx.x;
    const float* base = W + (size_t)r * I_DIM * O_DIM + o;
    float s = 0.f;
#pragma unroll 8
    for (int i = 0; i < I_DIM; i++) {
        s += base[(size_t)i * O_DIM];
    }
    g_wsum[r * O_DIM + o] = s;
}

// Packed fp32x2 FMA (Blackwell).
__device__ __forceinline__ unsigned long long ffma2(unsigned long long a,
                                                    unsigned long long b,
                                                    unsigned long long c) {
    unsigned long long d;
    asm("fma.rn.f32x2 %0, %1, %2, %3;" : "=l"(d) : "l"(a), "l"(b), "l"(c));
    return d;
}

__device__ __forceinline__ unsigned long long pack2(float lo, float hi) {
    unsigned long long v;
    asm("mov.b64 %0, {%1, %2};" : "=l"(v) : "f"(lo), "f"(hi));
    return v;
}

// ---------------------------------------------------------------------------
// Kernel 2 (fused main), r-chunked to keep regs <= 85 (6 blocks/SM):
//   xs[t]      = sum_j x[e,j]
//   csr2[t][r] = dup(xs[t] / cs[e,r])       (x_sum scale folded into csr)
//   out[e, 2t:2t+2] += W_sum[r, 2t:2t+2] (*) csr2[t][r]  via FFMA2
// ---------------------------------------------------------------------------
__global__ __launch_bounds__(MAIN_THREADS, 6)
void rgcn_main_kernel(const float* __restrict__ x,
                      const float* __restrict__ cs,
                      float* __restrict__ out,
                      int E) {
    __shared__ float xs[T_E];
    __shared__ __align__(16) unsigned long long csr2[T_E * R_DIM];

    const int tid  = threadIdx.x;
    const int e0   = blockIdx.x * T_E;
    const int warp = tid >> 5;
    const int lane = tid & 31;

    // --- Phase B: x row sums, one warp per row (2 rows per warp) ---
    for (int t = warp; t < T_E; t += MAIN_THREADS / 32) {
        const int e = e0 + t;
        float s = 0.f;
        if (e < E) {
            const float4* row = reinterpret_cast<const float4*>(x + (size_t)e * I_DIM);
            float4 a = row[lane];
            float4 b = row[lane + 32];
            s = (a.x + a.y) + (a.z + a.w) + (b.x + b.y) + (b.z + b.w);
        }
#pragma unroll
        for (int off = 16; off > 0; off >>= 1)
            s += __shfl_xor_sync(0xffffffffu, s, off);
        if (lane == 0) xs[t] = s;
    }
    __syncthreads();

    // --- Phase C: csr2[t][r] = dup(xs[t] / cs[e,r]), fast-reciprocal path ---
#pragma unroll
    for (int k = 0; k < (T_E * R_DIM) / MAIN_THREADS; k++) {
        const int idx = k * MAIN_THREADS + tid;
        const int t = idx >> 6;          // / R_DIM
        const int r = idx & (R_DIM - 1);
        const int e = e0 + t;
        float v = 0.f;
        if (e < E) v = __fdividef(xs[t], cs[(size_t)e * R_DIM + r]);
        csr2[idx] = pack2(v, v);
    }
    __syncthreads();

    // --- Phase D: r-chunked FFMA2 mainloop ---
    unsigned long long acc[T_E];
#pragma unroll
    for (int t = 0; t < T_E; t++) acc[t] = 0ull;

    const float2* wsum2 = reinterpret_cast<const float2*>(g_wsum);

#pragma unroll
    for (int rc = 0; rc < R_DIM / R_CHUNK; rc++) {
        // Load this chunk's W_sum column pair (coalesced LDG.64, L1-resident).
        unsigned long long w2[R_CHUNK];
#pragma unroll
        for (int i = 0; i < R_CHUNK; i++) {
            float2 v = wsum2[(rc * R_CHUNK + i) * (O_DIM / 2) + tid];
            w2[i] = pack2(v.x, v.y);
        }
#pragma unroll
        for (int rr = 0; rr < R_CHUNK; rr += 2) {
#pragma unroll
            for (int t = 0; t < T_E; t++) {
                ulonglong2 c = *reinterpret_cast<const ulonglong2*>(
                    &csr2[t * R_DIM + rc * R_CHUNK + rr]);
                acc[t] = ffma2(w2[rr],     c.x, acc[t]);
                acc[t] = ffma2(w2[rr + 1], c.y, acc[t]);
            }
        }
    }

    // --- Epilogue: packed 8B stores, coalesced per row ---
#pragma unroll
    for (int t = 0; t < T_E; t++) {
        const int e = e0 + t;
        if (e < E) {
            float2 v;
            asm("mov.b64 {%0, %1}, %2;" : "=f"(v.x), "=f"(v.y) : "l"(acc[t]));
            reinterpret_cast<float2*>(out)[(size_t)e * (O_DIM / 2) + tid] = v;
        }
    }
}

// ---------------------------------------------------------------------------
// Launch. Inputs: x (E*256 f32), cs (E*64 f32), W (64*256*256 f32),
// edge_index (2*N int64, unused by the reference math). Output: E*256 f32.
// ---------------------------------------------------------------------------
extern "C" void kernel_launch(void* const* d_in, const int* in_sizes, int n_in,
                              void* d_out, int out_size) {
    const float* x  = (const float*)d_in[0];
    const float* cs = (const float*)d_in[1];
    const float* W  = (const float*)d_in[2];
    float* out = (float*)d_out;

    const int E = in_sizes[0] / I_DIM;

    wsum_kernel<<<R_DIM, O_DIM>>>(W);
    const int grid = (E + T_E - 1) / T_E;
    rgcn_main_kernel<<<grid, MAIN_THREADS>>>(x, cs, out, E);
}

// round 3
// speedup vs baseline: 2.2980x; 1.3101x over previous
#include <cuda_runtime.h>
#include <cstdint>

// Problem constants (shapes fixed for this dataset entry).
#define R_DIM 64
#define I_DIM 256
#define O_DIM 256
#define TE_BLK 16          // entity rows per block (two groups of 8)
#define TE_GRP 8           // rows per 64-thread column-group
#define MAIN_THREADS 128
#define R_CHUNK 4          // w2 footprint = 2*R_CHUNK packed regs = 16 regs

// Scratch: W_sum[r][o].
__device__ float g_wsum[R_DIM * O_DIM];

// ---------------------------------------------------------------------------
// Kernel 1: W_sum[r][o] = sum_i W[r][i][o].  grid(64), block(256).
// ---------------------------------------------------------------------------
__global__ void wsum_kernel(const float* __restrict__ W) {
    const int r = blockIdx.x;
    const int o = threadIdx.x;
    const float* base = W + (size_t)r * I_DIM * O_DIM + o;
    float s = 0.f;
#pragma unroll 8
    for (int i = 0; i < I_DIM; i++) {
        s += base[(size_t)i * O_DIM];
    }
    g_wsum[r * O_DIM + o] = s;
}

// Packed fp32x2 FMA (Blackwell).
__device__ __forceinline__ unsigned long long ffma2(unsigned long long a,
                                                    unsigned long long b,
                                                    unsigned long long c) {
    unsigned long long d;
    asm("fma.rn.f32x2 %0, %1, %2, %3;" : "=l"(d) : "l"(a), "l"(b), "l"(c));
    return d;
}

__device__ __forceinline__ unsigned long long pack2(float lo, float hi) {
    unsigned long long v;
    asm("mov.b64 %0, {%1, %2};" : "=l"(v) : "f"(lo), "f"(hi));
    return v;
}

__device__ __forceinline__ void unpack2(unsigned long long v, float& lo, float& hi) {
    asm("mov.b64 {%0, %1}, %2;" : "=f"(lo), "=f"(hi) : "l"(v));
}

// ---------------------------------------------------------------------------
// Kernel 2 (fused main). Block tile: 16 rows x 256 cols.
// Thread layout: group g = tid>>6 owns rows [g*8, g*8+8); col-thread
// ct = tid&63 owns cols [4*ct, 4*ct+4) as two packed f32x2 accumulators.
// Mainloop ratio: 1 broadcast LDS.128 (csr pair, one row) : 4 FFMA2.
// ---------------------------------------------------------------------------
__global__ __launch_bounds__(MAIN_THREADS, 6)
void rgcn_main_kernel(const float* __restrict__ x,
                      const float* __restrict__ cs,
                      float* __restrict__ out,
                      int E) {
    __shared__ float xs[TE_BLK];
    __shared__ __align__(16) unsigned long long csr2[TE_BLK * R_DIM];

    const int tid  = threadIdx.x;
    const int e0   = blockIdx.x * TE_BLK;
    const int warp = tid >> 5;
    const int lane = tid & 31;
    const int grp  = tid >> 6;    // row-group 0/1
    const int ct   = tid & 63;    // column-thread within group

    // --- Phase B: x row sums; 4 warps x 4 rows each ---
#pragma unroll
    for (int k = 0; k < TE_BLK / 4; k++) {
        const int t = warp * (TE_BLK / 4) + k;
        const int e = e0 + t;
        float s = 0.f;
        if (e < E) {
            const float4* row = reinterpret_cast<const float4*>(x + (size_t)e * I_DIM);
            float4 a = row[lane];
            float4 b = row[lane + 32];
            s = (a.x + a.y) + (a.z + a.w) + (b.x + b.y) + (b.z + b.w);
        }
#pragma unroll
        for (int off = 16; off > 0; off >>= 1)
            s += __shfl_xor_sync(0xffffffffu, s, off);
        if (lane == 0) xs[t] = s;
    }
    __syncthreads();

    // --- Phase C: csr2[t][r] = dup(xs[t]/cs[e,r]) ---
#pragma unroll
    for (int k = 0; k < (TE_BLK * R_DIM) / MAIN_THREADS; k++) {
        const int idx = k * MAIN_THREADS + tid;
        const int t = idx >> 6;          // / R_DIM
        const int r = idx & (R_DIM - 1);
        const int e = e0 + t;
        float v = 0.f;
        if (e < E) v = __fdividef(xs[t], cs[(size_t)e * R_DIM + r]);
        csr2[idx] = pack2(v, v);
    }
    __syncthreads();

    // --- Phase D: r-chunked FFMA2 mainloop, O_PER=4 ---
    unsigned long long acc0[TE_GRP], acc1[TE_GRP];
#pragma unroll
    for (int t = 0; t < TE_GRP; t++) { acc0[t] = 0ull; acc1[t] = 0ull; }

    const float4* wsum4 = reinterpret_cast<const float4*>(g_wsum);
    const unsigned long long* csr_g = &csr2[grp * TE_GRP * R_DIM];

#pragma unroll
    for (int rc = 0; rc < R_DIM / R_CHUNK; rc++) {
        // This chunk's W_sum 4-col slab -> registers (LDG.128, coalesced, L1-hit)
        unsigned long long w0[R_CHUNK], w1[R_CHUNK];
#pragma unroll
        for (int i = 0; i < R_CHUNK; i++) {
            float4 v = wsum4[(rc * R_CHUNK + i) * (O_DIM / 4) + ct];
            w0[i] = pack2(v.x, v.y);
            w1[i] = pack2(v.z, v.w);
        }
#pragma unroll
        for (int rr = 0; rr < R_CHUNK; rr += 2) {
#pragma unroll
            for (int t = 0; t < TE_GRP; t++) {
                ulonglong2 c = *reinterpret_cast<const ulonglong2*>(
                    &csr_g[t * R_DIM + rc * R_CHUNK + rr]);
                acc0[t] = ffma2(w0[rr],     c.x, acc0[t]);
                acc1[t] = ffma2(w1[rr],     c.x, acc1[t]);
                acc0[t] = ffma2(w0[rr + 1], c.y, acc0[t]);
                acc1[t] = ffma2(w1[rr + 1], c.y, acc1[t]);
            }
        }
    }

    // --- Epilogue: STG.128 per row, coalesced ---
#pragma unroll
    for (int t = 0; t < TE_GRP; t++) {
        const int e = e0 + grp * TE_GRP + t;
        if (e < E) {
            float4 v;
            unpack2(acc0[t], v.x, v.y);
            unpack2(acc1[t], v.z, v.w);
            reinterpret_cast<float4*>(out)[(size_t)e * (O_DIM / 4) + ct] = v;
        }
    }
}

// ---------------------------------------------------------------------------
// Launch. Inputs: x (E*256 f32), cs (E*64 f32), W (64*256*256 f32),
// edge_index (2*N int64, unused by the reference math). Output: E*256 f32.
// ---------------------------------------------------------------------------
extern "C" void kernel_launch(void* const* d_in, const int* in_sizes, int n_in,
                              void* d_out, int out_size) {
    const float* x  = (const float*)d_in[0];
    const float* cs = (const float*)d_in[1];
    const float* W  = (const float*)d_in[2];
    float* out = (float*)d_out;

    const int E = in_sizes[0] / I_DIM;

    wsum_kernel<<<R_DIM, O_DIM>>>(W);
    const int grid = (E + TE_BLK - 1) / TE_BLK;
    rgcn_main_kernel<<<grid, MAIN_THREADS>>>(x, cs, out, E);
}

// round 4
// speedup vs baseline: 2.5879x; 1.1262x over previous
#include <cuda_runtime.h>
#include <cstdint>

// Problem constants (fixed shapes).
#define R_DIM 64
#define I_DIM 256
#define O_DIM 256
#define TE_BLK 16          // entity rows per block (8 row-pairs)
#define P_DIM  8           // row-pairs per block
#define MAIN_THREADS 128   // thread owns 2 adjacent output cols for 16 rows
#define I_SPLIT 8          // wsum parallel split over i

// Scratch (static __device__ — no allocs).
__device__ unsigned long long g_wdup[R_DIM * O_DIM];       // {w,w} per (r,o), 128KB
__device__ float g_wpart[I_SPLIT][R_DIM * O_DIM];          // 512KB partials

__device__ __forceinline__ unsigned long long ffma2(unsigned long long a,
                                                    unsigned long long b,
                                                    unsigned long long c) {
    unsigned long long d;
    asm("fma.rn.f32x2 %0, %1, %2, %3;" : "=l"(d) : "l"(a), "l"(b), "l"(c));
    return d;
}
__device__ __forceinline__ unsigned long long pack2(float lo, float hi) {
    unsigned long long v;
    asm("mov.b64 %0, {%1, %2};" : "=l"(v) : "f"(lo), "f"(hi));
    return v;
}
__device__ __forceinline__ void unpack2(unsigned long long v, float& lo, float& hi) {
    asm("mov.b64 {%0, %1}, %2;" : "=f"(lo), "=f"(hi) : "l"(v));
}

// ---------------------------------------------------------------------------
// Kernel 1a: partial W sums. grid(64, I_SPLIT), block(256).
// ---------------------------------------------------------------------------
__global__ void wsum_part_kernel(const float* __restrict__ W) {
    const int r  = blockIdx.x;
    const int iy = blockIdx.y;
    const int o  = threadIdx.x;
    const float* base = W + (size_t)r * I_DIM * O_DIM
                          + (size_t)iy * (I_DIM / I_SPLIT) * O_DIM + o;
    float s = 0.f;
#pragma unroll 8
    for (int i = 0; i < I_DIM / I_SPLIT; i++) s += base[(size_t)i * O_DIM];
    g_wpart[iy][r * O_DIM + o] = s;
}

// Kernel 1b: reduce partials, write duplicated-packed W_sum. grid(64), block(256).
__global__ void wsum_fin_kernel() {
    const int r = blockIdx.x;
    const int o = threadIdx.x;
    float s = 0.f;
#pragma unroll
    for (int iy = 0; iy < I_SPLIT; iy++) s += g_wpart[iy][r * O_DIM + o];
    g_wdup[r * O_DIM + o] = pack2(s, s);
}

// ---------------------------------------------------------------------------
// Kernel 2 (fused main). Block tile: 16 rows x 256 cols, 128 threads.
// acc[p][c] (packed f32x2) = {out[2p][c], out[2p+1][c]} for thread cols
// c0=2*tid, c1=2*tid+1.  Inner: acc[p][c] += {w,w}[r][c] * {csr2p, csr2p+1}[r].
// Per r per thread: 4 broadcast LDS.128 + 1 LDG.128 + 16 FFMA2.
// ---------------------------------------------------------------------------
__global__ __launch_bounds__(MAIN_THREADS, 6)
void rgcn_main_kernel(const float* __restrict__ x,
                      const float* __restrict__ cs,
                      float* __restrict__ out,
                      int E) {
    __shared__ float xs[TE_BLK];
    __shared__ __align__(16) unsigned long long csrp[R_DIM * P_DIM]; // [r][p], 4KB

    const int tid  = threadIdx.x;
    const int e0   = blockIdx.x * TE_BLK;
    const int warp = tid >> 5;
    const int lane = tid & 31;

    // --- Phase B: x row sums; warp w handles rows 4w..4w+3 ---
#pragma unroll
    for (int k = 0; k < TE_BLK / 4; k++) {
        const int t = warp * (TE_BLK / 4) + k;
        const int e = e0 + t;
        float s = 0.f;
        if (e < E) {
            const float4* row = reinterpret_cast<const float4*>(x + (size_t)e * I_DIM);
            float4 a = row[lane];
            float4 b = row[lane + 32];
            s = (a.x + a.y) + (a.z + a.w) + (b.x + b.y) + (b.z + b.w);
        }
#pragma unroll
        for (int off = 16; off > 0; off >>= 1)
            s += __shfl_xor_sync(0xffffffffu, s, off);
        if (lane == 0) xs[t] = s;
    }
    __syncthreads();

    // --- Phase C: csrp[r][p] = {xs[2p]/cs[e0+2p][r], xs[2p+1]/cs[e0+2p+1][r]} ---
#pragma unroll
    for (int k = 0; k < (R_DIM * P_DIM) / MAIN_THREADS; k++) {
        const int idx = k * MAIN_THREADS + tid;
        const int r = idx >> 3;          // / P_DIM
        const int p = idx & (P_DIM - 1);
        const int ea = e0 + 2 * p;
        const int eb = ea + 1;
        float va = 0.f, vb = 0.f;
        if (ea < E) va = __fdividef(xs[2 * p],     cs[(size_t)ea * R_DIM + r]);
        if (eb < E) vb = __fdividef(xs[2 * p + 1], cs[(size_t)eb * R_DIM + r]);
        csrp[idx] = pack2(va, vb);
    }
    __syncthreads();

    // --- Phase D: FFMA2 mainloop ---
    unsigned long long acc0[P_DIM], acc1[P_DIM];
#pragma unroll
    for (int p = 0; p < P_DIM; p++) { acc0[p] = 0ull; acc1[p] = 0ull; }

    const ulonglong2* wdup2 = reinterpret_cast<const ulonglong2*>(g_wdup); // [r][c/2]

#pragma unroll 4
    for (int r = 0; r < R_DIM; r++) {
        // This thread's two duplicated W columns for relation r (LDG.128, L1-hot).
        ulonglong2 w = wdup2[r * (O_DIM / 2) + tid];
        // All 8 row-pair csr values for relation r (broadcast LDS.128 x4).
        const ulonglong2* c4 = reinterpret_cast<const ulonglong2*>(&csrp[r * P_DIM]);
        ulonglong2 c01 = c4[0], c23 = c4[1], c45 = c4[2], c67 = c4[3];

        acc0[0] = ffma2(w.x, c01.x, acc0[0]);  acc1[0] = ffma2(w.y, c01.x, acc1[0]);
        acc0[1] = ffma2(w.x, c01.y, acc0[1]);  acc1[1] = ffma2(w.y, c01.y, acc1[1]);
        acc0[2] = ffma2(w.x, c23.x, acc0[2]);  acc1[2] = ffma2(w.y, c23.x, acc1[2]);
        acc0[3] = ffma2(w.x, c23.y, acc0[3]);  acc1[3] = ffma2(w.y, c23.y, acc1[3]);
        acc0[4] = ffma2(w.x, c45.x, acc0[4]);  acc1[4] = ffma2(w.y, c45.x, acc1[4]);
        acc0[5] = ffma2(w.x, c45.y, acc0[5]);  acc1[5] = ffma2(w.y, c45.y, acc1[5]);
        acc0[6] = ffma2(w.x, c67.x, acc0[6]);  acc1[6] = ffma2(w.y, c67.x, acc1[6]);
        acc0[7] = ffma2(w.x, c67.y, acc0[7]);  acc1[7] = ffma2(w.y, c67.y, acc1[7]);
    }

    // --- Epilogue: two coalesced float2 stores per row-pair ---
    float2* out2 = reinterpret_cast<float2*>(out);
#pragma unroll
    for (int p = 0; p < P_DIM; p++) {
        const int ea = e0 + 2 * p;
        const int eb = ea + 1;
        float a_lo, a_hi, b_lo, b_hi;
        unpack2(acc0[p], a_lo, a_hi);   // rows 2p / 2p+1, col c0
        unpack2(acc1[p], b_lo, b_hi);   // rows 2p / 2p+1, col c1
        if (ea < E) out2[(size_t)ea * (O_DIM / 2) + tid] = make_float2(a_lo, b_lo);
        if (eb < E) out2[(size_t)eb * (O_DIM / 2) + tid] = make_float2(a_hi, b_hi);
    }
}

// ---------------------------------------------------------------------------
// Launch. Inputs: x (E*256 f32), cs (E*64 f32), W (64*256*256 f32),
// edge_index (unused by the factorized math). Output: E*256 f32.
// ---------------------------------------------------------------------------
extern "C" void kernel_launch(void* const* d_in, const int* in_sizes, int n_in,
                              void* d_out, int out_size) {
    const float* x  = (const float*)d_in[0];
    const float* cs = (const float*)d_in[1];
    const float* W  = (const float*)d_in[2];
    float* out = (float*)d_out;

    const int E = in_sizes[0] / I_DIM;

    wsum_part_kernel<<<dim3(R_DIM, I_SPLIT), O_DIM>>>(W);
    wsum_fin_kernel<<<R_DIM, O_DIM>>>();
    const int grid = (E + TE_BLK - 1) / TE_BLK;
    rgcn_main_kernel<<<grid, MAIN_THREADS>>>(x, cs, out, E);
}